// round 3
// baseline (speedup 1.0000x reference)
#include <cuda_runtime.h>
#include <math.h>

#define NCTX 4096
#define DM   2048
#define NEG_INF (-3.402823466e38f)

// Scratch (device globals -- no runtime allocation allowed)
__device__ float g_q[(size_t)NCTX * DM];        // 32 MB : x @ Wqk^T
__device__ float g_s[(size_t)NCTX * NCTX];      // 64 MB : scores / attn probs
__device__ float g_h[(size_t)NCTX * DM];        // 32 MB : attn @ x

// ---------------------------------------------------------------------------
// C[M,Nn] = A[M,K] * B[Nn,K]^T   (both operands row-major, K contiguous)
// 128x128 tile, BK=16, 256 threads, 8x8 per thread.
// MASK=true: causal score GEMM -- blocks fully above the diagonal are filled
// with NEG_INF without touching the K loop; crossing blocks mask per element.
// ---------------------------------------------------------------------------
template<bool MASK>
__global__ __launch_bounds__(256, 2)
void gemm_abt(const float* __restrict__ A, const float* __restrict__ B,
              float* __restrict__ C, int M, int Nn, int K)
{
    __shared__ float As[16][128];
    __shared__ float Bs[16][128];
    const int tid = threadIdx.x;
    const int i0 = blockIdx.y * 128;
    const int j0 = blockIdx.x * 128;
    const int ty = tid >> 4;
    const int tx = tid & 15;

    if (MASK && j0 >= i0 + 128) {
        // Entire tile is above the diagonal: just splat NEG_INF.
        const float4 neg = make_float4(NEG_INF, NEG_INF, NEG_INF, NEG_INF);
        #pragma unroll
        for (int m = 0; m < 8; ++m) {
            size_t base = (size_t)(i0 + ty * 8 + m) * Nn + j0 + tx * 8;
            *(float4*)&C[base]     = neg;
            *(float4*)&C[base + 4] = neg;
        }
        return;
    }

    float acc[8][8];
    #pragma unroll
    for (int m = 0; m < 8; ++m)
        #pragma unroll
        for (int n = 0; n < 8; ++n) acc[m][n] = 0.f;

    for (int k0 = 0; k0 < K; k0 += 16) {
        // Stage 128x16 tiles of A and B (transposed into [k][row] layout).
        #pragma unroll
        for (int l = 0; l < 2; ++l) {
            int v   = tid + l * 256;      // float4 id in [0,512)
            int row = v >> 2;             // 4 float4 per row of 16
            int c4  = (v & 3) * 4;
            float4 a = *(const float4*)&A[(size_t)(i0 + row) * K + k0 + c4];
            As[c4 + 0][row] = a.x; As[c4 + 1][row] = a.y;
            As[c4 + 2][row] = a.z; As[c4 + 3][row] = a.w;
            float4 b = *(const float4*)&B[(size_t)(j0 + row) * K + k0 + c4];
            Bs[c4 + 0][row] = b.x; Bs[c4 + 1][row] = b.y;
            Bs[c4 + 2][row] = b.z; Bs[c4 + 3][row] = b.w;
        }
        __syncthreads();

        #pragma unroll
        for (int kk = 0; kk < 16; ++kk) {
            float4 a0 = *(float4*)&As[kk][ty * 8];
            float4 a1 = *(float4*)&As[kk][ty * 8 + 4];
            float4 b0 = *(float4*)&Bs[kk][tx * 8];
            float4 b1 = *(float4*)&Bs[kk][tx * 8 + 4];
            float av[8] = {a0.x, a0.y, a0.z, a0.w, a1.x, a1.y, a1.z, a1.w};
            float bv[8] = {b0.x, b0.y, b0.z, b0.w, b1.x, b1.y, b1.z, b1.w};
            #pragma unroll
            for (int m = 0; m < 8; ++m)
                #pragma unroll
                for (int n = 0; n < 8; ++n)
                    acc[m][n] = fmaf(av[m], bv[n], acc[m][n]);
        }
        __syncthreads();
    }

    #pragma unroll
    for (int m = 0; m < 8; ++m) {
        int i = i0 + ty * 8 + m;
        size_t base = (size_t)i * Nn + j0 + tx * 8;
        if (MASK) {
            #pragma unroll
            for (int n = 0; n < 8; ++n) {
                int j = j0 + tx * 8 + n;
                if (j > i) acc[m][n] = NEG_INF;
            }
        }
        float4 w0 = make_float4(acc[m][0], acc[m][1], acc[m][2], acc[m][3]);
        float4 w1 = make_float4(acc[m][4], acc[m][5], acc[m][6], acc[m][7]);
        *(float4*)&C[base]     = w0;
        *(float4*)&C[base + 4] = w1;
    }
}

// ---------------------------------------------------------------------------
// C[M,Nn] = A[M,K] * B[K,Nn]   (standard NN GEMM). causal!=0 clamps the K loop
// to the lower triangle of A (attn is exactly 0 above the diagonal).
// ---------------------------------------------------------------------------
__global__ __launch_bounds__(256, 2)
void gemm_ab(const float* __restrict__ A, const float* __restrict__ B,
             float* __restrict__ C, int M, int Nn, int K, int causal)
{
    __shared__ float As[16][128];
    __shared__ float Bs[16][128];
    const int tid = threadIdx.x;
    const int i0 = blockIdx.y * 128;
    const int j0 = blockIdx.x * 128;
    const int ty = tid >> 4;
    const int tx = tid & 15;

    int kend = causal ? (i0 + 128) : K;
    if (kend > K) kend = K;

    float acc[8][8];
    #pragma unroll
    for (int m = 0; m < 8; ++m)
        #pragma unroll
        for (int n = 0; n < 8; ++n) acc[m][n] = 0.f;

    for (int k0 = 0; k0 < kend; k0 += 16) {
        #pragma unroll
        for (int l = 0; l < 2; ++l) {
            int v   = tid + l * 256;
            int row = v >> 2;
            int c4  = (v & 3) * 4;
            float4 a = *(const float4*)&A[(size_t)(i0 + row) * K + k0 + c4];
            As[c4 + 0][row] = a.x; As[c4 + 1][row] = a.y;
            As[c4 + 2][row] = a.z; As[c4 + 3][row] = a.w;
            // B tile: 16 rows x 128 cols, contiguous in j.
            int kr = v >> 5;
            int jc = (v & 31) * 4;
            *(float4*)&Bs[kr][jc] = *(const float4*)&B[(size_t)(k0 + kr) * Nn + j0 + jc];
        }
        __syncthreads();

        #pragma unroll
        for (int kk = 0; kk < 16; ++kk) {
            float4 a0 = *(float4*)&As[kk][ty * 8];
            float4 a1 = *(float4*)&As[kk][ty * 8 + 4];
            float4 b0 = *(float4*)&Bs[kk][tx * 8];
            float4 b1 = *(float4*)&Bs[kk][tx * 8 + 4];
            float av[8] = {a0.x, a0.y, a0.z, a0.w, a1.x, a1.y, a1.z, a1.w};
            float bv[8] = {b0.x, b0.y, b0.z, b0.w, b1.x, b1.y, b1.z, b1.w};
            #pragma unroll
            for (int m = 0; m < 8; ++m)
                #pragma unroll
                for (int n = 0; n < 8; ++n)
                    acc[m][n] = fmaf(av[m], bv[n], acc[m][n]);
        }
        __syncthreads();
    }

    #pragma unroll
    for (int m = 0; m < 8; ++m) {
        size_t base = (size_t)(i0 + ty * 8 + m) * Nn + j0 + tx * 8;
        float4 w0 = make_float4(acc[m][0], acc[m][1], acc[m][2], acc[m][3]);
        float4 w1 = make_float4(acc[m][4], acc[m][5], acc[m][6], acc[m][7]);
        *(float4*)&C[base]     = w0;
        *(float4*)&C[base + 4] = w1;
    }
}

// ---------------------------------------------------------------------------
// Row softmax over NCTX entries, one block per row; the row (16 KB) stays in
// registers (16 floats/thread), single read + single write of g_s.
// Masked entries hold NEG_INF -> expf underflows to exactly 0.
// ---------------------------------------------------------------------------
__global__ __launch_bounds__(256)
void softmax_rows(float* __restrict__ S)
{
    const int row = blockIdx.x;
    const int tid = threadIdx.x;
    float* srow = S + (size_t)row * NCTX;

    float4 v[4];
    float vmax = NEG_INF;
    #pragma unroll
    for (int l = 0; l < 4; ++l) {
        v[l] = *(float4*)&srow[(tid + l * 256) * 4];
        vmax = fmaxf(vmax, fmaxf(fmaxf(v[l].x, v[l].y), fmaxf(v[l].z, v[l].w)));
    }

    __shared__ float red[256];
    red[tid] = vmax;
    __syncthreads();
    #pragma unroll
    for (int s = 128; s > 0; s >>= 1) {
        if (tid < s) red[tid] = fmaxf(red[tid], red[tid + s]);
        __syncthreads();
    }
    vmax = red[0];
    __syncthreads();

    float sum = 0.f;
    #pragma unroll
    for (int l = 0; l < 4; ++l) {
        v[l].x = expf(v[l].x - vmax);
        v[l].y = expf(v[l].y - vmax);
        v[l].z = expf(v[l].z - vmax);
        v[l].w = expf(v[l].w - vmax);
        sum += (v[l].x + v[l].y) + (v[l].z + v[l].w);
    }
    red[tid] = sum;
    __syncthreads();
    #pragma unroll
    for (int s = 128; s > 0; s >>= 1) {
        if (tid < s) red[tid] += red[tid + s];
        __syncthreads();
    }
    float inv = 1.f / red[0];

    #pragma unroll
    for (int l = 0; l < 4; ++l) {
        v[l].x *= inv; v[l].y *= inv; v[l].z *= inv; v[l].w *= inv;
        *(float4*)&srow[(tid + l * 256) * 4] = v[l];
    }
}

// ---------------------------------------------------------------------------

extern "C" void kernel_launch(void* const* d_in, const int* in_sizes, int n_in,
                              void* d_out, int out_size)
{
    const float* x   = (const float*)d_in[0];   // [4096, 2048]
    const float* Wqk = (const float*)d_in[1];   // [2048, 2048]
    const float* Wov = (const float*)d_in[2];   // [2048, 2048]
    float* out = (float*)d_out;                 // [4096, 2048]

    float *q, *s, *h;
    cudaGetSymbolAddress((void**)&q, g_q);
    cudaGetSymbolAddress((void**)&s, g_s);
    cudaGetSymbolAddress((void**)&h, g_h);

    dim3 blk(256);
    // q = x @ Wqk^T
    gemm_abt<false><<<dim3(DM / 128, NCTX / 128), blk>>>(x, Wqk, q, NCTX, DM, DM);
    // scores = q @ x^T  (+ causal mask)
    gemm_abt<true ><<<dim3(NCTX / 128, NCTX / 128), blk>>>(q, x, s, NCTX, NCTX, DM);
    // attn = softmax(scores) rowwise (in place)
    softmax_rows<<<NCTX, blk>>>(s);
    // h = attn @ x  (K loop clamped to lower triangle)
    gemm_ab<<<dim3(DM / 128, NCTX / 128), blk>>>(s, x, h, NCTX, DM, NCTX, 1);
    // out = h @ Wov^T
    gemm_abt<false><<<dim3(DM / 128, NCTX / 128), blk>>>(h, Wov, out, NCTX, DM, DM);
}

// round 8
// speedup vs baseline: 1.0011x; 1.0011x over previous
#include <cuda_runtime.h>
#include <math.h>

#define NCTX 4096
#define DM   2048
#define NEG_INF (-3.402823466e38f)

// Scratch (device globals -- no runtime allocation allowed)
__device__ float g_q[(size_t)NCTX * DM];        // 32 MB : x @ Wqk^T
__device__ float g_s[(size_t)NCTX * NCTX];      // 64 MB : scores / attn probs
__device__ float g_h[(size_t)NCTX * DM];        // 32 MB : attn @ x

// ---------------------------------------------------------------------------
// C[M,Nn] = A[M,K] * B[Nn,K]^T   (both operands row-major, K contiguous)
// 128x128 tile, BK=16, 256 threads, 8x8 per thread.
// MASK=true: causal score GEMM -- blocks fully above the diagonal are filled
// with NEG_INF without touching the K loop; crossing blocks mask per element.
// ---------------------------------------------------------------------------
template<bool MASK>
__global__ __launch_bounds__(256, 2)
void gemm_abt(const float* __restrict__ A, const float* __restrict__ B,
              float* __restrict__ C, int M, int Nn, int K)
{
    __shared__ float As[16][128];
    __shared__ float Bs[16][128];
    const int tid = threadIdx.x;
    const int i0 = blockIdx.y * 128;
    const int j0 = blockIdx.x * 128;
    const int ty = tid >> 4;
    const int tx = tid & 15;

    if (MASK && j0 >= i0 + 128) {
        // Entire tile is above the diagonal: just splat NEG_INF.
        const float4 neg = make_float4(NEG_INF, NEG_INF, NEG_INF, NEG_INF);
        #pragma unroll
        for (int m = 0; m < 8; ++m) {
            size_t base = (size_t)(i0 + ty * 8 + m) * Nn + j0 + tx * 8;
            *(float4*)&C[base]     = neg;
            *(float4*)&C[base + 4] = neg;
        }
        return;
    }

    float acc[8][8];
    #pragma unroll
    for (int m = 0; m < 8; ++m)
        #pragma unroll
        for (int n = 0; n < 8; ++n) acc[m][n] = 0.f;

    for (int k0 = 0; k0 < K; k0 += 16) {
        // Stage 128x16 tiles of A and B (transposed into [k][row] layout).
        #pragma unroll
        for (int l = 0; l < 2; ++l) {
            int v   = tid + l * 256;      // float4 id in [0,512)
            int row = v >> 2;             // 4 float4 per row of 16
            int c4  = (v & 3) * 4;
            float4 a = *(const float4*)&A[(size_t)(i0 + row) * K + k0 + c4];
            As[c4 + 0][row] = a.x; As[c4 + 1][row] = a.y;
            As[c4 + 2][row] = a.z; As[c4 + 3][row] = a.w;
            float4 b = *(const float4*)&B[(size_t)(j0 + row) * K + k0 + c4];
            Bs[c4 + 0][row] = b.x; Bs[c4 + 1][row] = b.y;
            Bs[c4 + 2][row] = b.z; Bs[c4 + 3][row] = b.w;
        }
        __syncthreads();

        #pragma unroll
        for (int kk = 0; kk < 16; ++kk) {
            float4 a0 = *(float4*)&As[kk][ty * 8];
            float4 a1 = *(float4*)&As[kk][ty * 8 + 4];
            float4 b0 = *(float4*)&Bs[kk][tx * 8];
            float4 b1 = *(float4*)&Bs[kk][tx * 8 + 4];
            float av[8] = {a0.x, a0.y, a0.z, a0.w, a1.x, a1.y, a1.z, a1.w};
            float bv[8] = {b0.x, b0.y, b0.z, b0.w, b1.x, b1.y, b1.z, b1.w};
            #pragma unroll
            for (int m = 0; m < 8; ++m)
                #pragma unroll
                for (int n = 0; n < 8; ++n)
                    acc[m][n] = fmaf(av[m], bv[n], acc[m][n]);
        }
        __syncthreads();
    }

    #pragma unroll
    for (int m = 0; m < 8; ++m) {
        int i = i0 + ty * 8 + m;
        size_t base = (size_t)i * Nn + j0 + tx * 8;
        if (MASK) {
            #pragma unroll
            for (int n = 0; n < 8; ++n) {
                int j = j0 + tx * 8 + n;
                if (j > i) acc[m][n] = NEG_INF;
            }
        }
        float4 w0 = make_float4(acc[m][0], acc[m][1], acc[m][2], acc[m][3]);
        float4 w1 = make_float4(acc[m][4], acc[m][5], acc[m][6], acc[m][7]);
        *(float4*)&C[base]     = w0;
        *(float4*)&C[base + 4] = w1;
    }
}

// ---------------------------------------------------------------------------
// C[M,Nn] = A[M,K] * B[K,Nn]   (standard NN GEMM). causal!=0 clamps the K loop
// to the lower triangle of A (attn is exactly 0 above the diagonal).
// ---------------------------------------------------------------------------
__global__ __launch_bounds__(256, 2)
void gemm_ab(const float* __restrict__ A, const float* __restrict__ B,
             float* __restrict__ C, int M, int Nn, int K, int causal)
{
    __shared__ float As[16][128];
    __shared__ float Bs[16][128];
    const int tid = threadIdx.x;
    const int i0 = blockIdx.y * 128;
    const int j0 = blockIdx.x * 128;
    const int ty = tid >> 4;
    const int tx = tid & 15;

    int kend = causal ? (i0 + 128) : K;
    if (kend > K) kend = K;

    float acc[8][8];
    #pragma unroll
    for (int m = 0; m < 8; ++m)
        #pragma unroll
        for (int n = 0; n < 8; ++n) acc[m][n] = 0.f;

    for (int k0 = 0; k0 < kend; k0 += 16) {
        #pragma unroll
        for (int l = 0; l < 2; ++l) {
            int v   = tid + l * 256;
            int row = v >> 2;
            int c4  = (v & 3) * 4;
            float4 a = *(const float4*)&A[(size_t)(i0 + row) * K + k0 + c4];
            As[c4 + 0][row] = a.x; As[c4 + 1][row] = a.y;
            As[c4 + 2][row] = a.z; As[c4 + 3][row] = a.w;
            // B tile: 16 rows x 128 cols, contiguous in j.
            int kr = v >> 5;
            int jc = (v & 31) * 4;
            *(float4*)&Bs[kr][jc] = *(const float4*)&B[(size_t)(k0 + kr) * Nn + j0 + jc];
        }
        __syncthreads();

        #pragma unroll
        for (int kk = 0; kk < 16; ++kk) {
            float4 a0 = *(float4*)&As[kk][ty * 8];
            float4 a1 = *(float4*)&As[kk][ty * 8 + 4];
            float4 b0 = *(float4*)&Bs[kk][tx * 8];
            float4 b1 = *(float4*)&Bs[kk][tx * 8 + 4];
            float av[8] = {a0.x, a0.y, a0.z, a0.w, a1.x, a1.y, a1.z, a1.w};
            float bv[8] = {b0.x, b0.y, b0.z, b0.w, b1.x, b1.y, b1.z, b1.w};
            #pragma unroll
            for (int m = 0; m < 8; ++m)
                #pragma unroll
                for (int n = 0; n < 8; ++n)
                    acc[m][n] = fmaf(av[m], bv[n], acc[m][n]);
        }
        __syncthreads();
    }

    #pragma unroll
    for (int m = 0; m < 8; ++m) {
        size_t base = (size_t)(i0 + ty * 8 + m) * Nn + j0 + tx * 8;
        float4 w0 = make_float4(acc[m][0], acc[m][1], acc[m][2], acc[m][3]);
        float4 w1 = make_float4(acc[m][4], acc[m][5], acc[m][6], acc[m][7]);
        *(float4*)&C[base]     = w0;
        *(float4*)&C[base + 4] = w1;
    }
}

// ---------------------------------------------------------------------------
// Row softmax over NCTX entries, one block per row; the row (16 KB) stays in
// registers (16 floats/thread), single read + single write of g_s.
// Masked entries hold NEG_INF -> expf underflows to exactly 0.
// ---------------------------------------------------------------------------
__global__ __launch_bounds__(256)
void softmax_rows(float* __restrict__ S)
{
    const int row = blockIdx.x;
    const int tid = threadIdx.x;
    float* srow = S + (size_t)row * NCTX;

    float4 v[4];
    float vmax = NEG_INF;
    #pragma unroll
    for (int l = 0; l < 4; ++l) {
        v[l] = *(float4*)&srow[(tid + l * 256) * 4];
        vmax = fmaxf(vmax, fmaxf(fmaxf(v[l].x, v[l].y), fmaxf(v[l].z, v[l].w)));
    }

    __shared__ float red[256];
    red[tid] = vmax;
    __syncthreads();
    #pragma unroll
    for (int s = 128; s > 0; s >>= 1) {
        if (tid < s) red[tid] = fmaxf(red[tid], red[tid + s]);
        __syncthreads();
    }
    vmax = red[0];
    __syncthreads();

    float sum = 0.f;
    #pragma unroll
    for (int l = 0; l < 4; ++l) {
        v[l].x = expf(v[l].x - vmax);
        v[l].y = expf(v[l].y - vmax);
        v[l].z = expf(v[l].z - vmax);
        v[l].w = expf(v[l].w - vmax);
        sum += (v[l].x + v[l].y) + (v[l].z + v[l].w);
    }
    red[tid] = sum;
    __syncthreads();
    #pragma unroll
    for (int s = 128; s > 0; s >>= 1) {
        if (tid < s) red[tid] += red[tid + s];
        __syncthreads();
    }
    float inv = 1.f / red[0];

    #pragma unroll
    for (int l = 0; l < 4; ++l) {
        v[l].x *= inv; v[l].y *= inv; v[l].z *= inv; v[l].w *= inv;
        *(float4*)&srow[(tid + l * 256) * 4] = v[l];
    }
}

// ---------------------------------------------------------------------------

extern "C" void kernel_launch(void* const* d_in, const int* in_sizes, int n_in,
                              void* d_out, int out_size)
{
    const float* x   = (const float*)d_in[0];   // [4096, 2048]
    const float* Wqk = (const float*)d_in[1];   // [2048, 2048]
    const float* Wov = (const float*)d_in[2];   // [2048, 2048]
    float* out = (float*)d_out;                 // [4096, 2048]

    float *q, *s, *h;
    cudaGetSymbolAddress((void**)&q, g_q);
    cudaGetSymbolAddress((void**)&s, g_s);
    cudaGetSymbolAddress((void**)&h, g_h);

    dim3 blk(256);
    // q = x @ Wqk^T
    gemm_abt<false><<<dim3(DM / 128, NCTX / 128), blk>>>(x, Wqk, q, NCTX, DM, DM);
    // scores = q @ x^T  (+ causal mask)
    gemm_abt<true ><<<dim3(NCTX / 128, NCTX / 128), blk>>>(q, x, s, NCTX, NCTX, DM);
    // attn = softmax(scores) rowwise (in place)
    softmax_rows<<<NCTX, blk>>>(s);
    // h = attn @ x  (K loop clamped to lower triangle)
    gemm_ab<<<dim3(DM / 128, NCTX / 128), blk>>>(s, x, h, NCTX, DM, NCTX, 1);
    // out = h @ Wov^T
    gemm_abt<false><<<dim3(DM / 128, NCTX / 128), blk>>>(h, Wov, out, NCTX, DM, DM);
}

// round 9
// speedup vs baseline: 1.0023x; 1.0012x over previous
#include <cuda_runtime.h>
#include <math.h>

#define NCTX 4096
#define DM   2048
#define NEG_INF (-3.402823466e38f)

// Scratch (device globals -- no runtime allocation allowed)
__device__ float g_q[(size_t)NCTX * DM];        // 32 MB : x @ Wqk^T
__device__ float g_s[(size_t)NCTX * NCTX];      // 64 MB : scores / attn probs
__device__ float g_h[(size_t)NCTX * DM];        // 32 MB : attn @ x

// ---------------------------------------------------------------------------
// C[M,Nn] = A[M,K] * B[Nn,K]^T   (both operands row-major, K contiguous)
// 128x128 tile, BK=16, 256 threads, 8x8 per thread.
// MASK=true: causal score GEMM -- blocks fully above the diagonal are filled
// with NEG_INF without touching the K loop; crossing blocks mask per element.
// ---------------------------------------------------------------------------
template<bool MASK>
__global__ __launch_bounds__(256, 2)
void gemm_abt(const float* __restrict__ A, const float* __restrict__ B,
              float* __restrict__ C, int M, int Nn, int K)
{
    __shared__ float As[16][128];
    __shared__ float Bs[16][128];
    const int tid = threadIdx.x;
    const int i0 = blockIdx.y * 128;
    const int j0 = blockIdx.x * 128;
    const int ty = tid >> 4;
    const int tx = tid & 15;

    if (MASK && j0 >= i0 + 128) {
        // Entire tile is above the diagonal: just splat NEG_INF.
        const float4 neg = make_float4(NEG_INF, NEG_INF, NEG_INF, NEG_INF);
        #pragma unroll
        for (int m = 0; m < 8; ++m) {
            size_t base = (size_t)(i0 + ty * 8 + m) * Nn + j0 + tx * 8;
            *(float4*)&C[base]     = neg;
            *(float4*)&C[base + 4] = neg;
        }
        return;
    }

    float acc[8][8];
    #pragma unroll
    for (int m = 0; m < 8; ++m)
        #pragma unroll
        for (int n = 0; n < 8; ++n) acc[m][n] = 0.f;

    for (int k0 = 0; k0 < K; k0 += 16) {
        // Stage 128x16 tiles of A and B (transposed into [k][row] layout).
        #pragma unroll
        for (int l = 0; l < 2; ++l) {
            int v   = tid + l * 256;      // float4 id in [0,512)
            int row = v >> 2;             // 4 float4 per row of 16
            int c4  = (v & 3) * 4;
            float4 a = *(const float4*)&A[(size_t)(i0 + row) * K + k0 + c4];
            As[c4 + 0][row] = a.x; As[c4 + 1][row] = a.y;
            As[c4 + 2][row] = a.z; As[c4 + 3][row] = a.w;
            float4 b = *(const float4*)&B[(size_t)(j0 + row) * K + k0 + c4];
            Bs[c4 + 0][row] = b.x; Bs[c4 + 1][row] = b.y;
            Bs[c4 + 2][row] = b.z; Bs[c4 + 3][row] = b.w;
        }
        __syncthreads();

        #pragma unroll
        for (int kk = 0; kk < 16; ++kk) {
            float4 a0 = *(float4*)&As[kk][ty * 8];
            float4 a1 = *(float4*)&As[kk][ty * 8 + 4];
            float4 b0 = *(float4*)&Bs[kk][tx * 8];
            float4 b1 = *(float4*)&Bs[kk][tx * 8 + 4];
            float av[8] = {a0.x, a0.y, a0.z, a0.w, a1.x, a1.y, a1.z, a1.w};
            float bv[8] = {b0.x, b0.y, b0.z, b0.w, b1.x, b1.y, b1.z, b1.w};
            #pragma unroll
            for (int m = 0; m < 8; ++m)
                #pragma unroll
                for (int n = 0; n < 8; ++n)
                    acc[m][n] = fmaf(av[m], bv[n], acc[m][n]);
        }
        __syncthreads();
    }

    #pragma unroll
    for (int m = 0; m < 8; ++m) {
        int i = i0 + ty * 8 + m;
        size_t base = (size_t)i * Nn + j0 + tx * 8;
        if (MASK) {
            #pragma unroll
            for (int n = 0; n < 8; ++n) {
                int j = j0 + tx * 8 + n;
                if (j > i) acc[m][n] = NEG_INF;
            }
        }
        float4 w0 = make_float4(acc[m][0], acc[m][1], acc[m][2], acc[m][3]);
        float4 w1 = make_float4(acc[m][4], acc[m][5], acc[m][6], acc[m][7]);
        *(float4*)&C[base]     = w0;
        *(float4*)&C[base + 4] = w1;
    }
}

// ---------------------------------------------------------------------------
// C[M,Nn] = A[M,K] * B[K,Nn]   (standard NN GEMM). causal!=0 clamps the K loop
// to the lower triangle of A (attn is exactly 0 above the diagonal).
// ---------------------------------------------------------------------------
__global__ __launch_bounds__(256, 2)
void gemm_ab(const float* __restrict__ A, const float* __restrict__ B,
             float* __restrict__ C, int M, int Nn, int K, int causal)
{
    __shared__ float As[16][128];
    __shared__ float Bs[16][128];
    const int tid = threadIdx.x;
    const int i0 = blockIdx.y * 128;
    const int j0 = blockIdx.x * 128;
    const int ty = tid >> 4;
    const int tx = tid & 15;

    int kend = causal ? (i0 + 128) : K;
    if (kend > K) kend = K;

    float acc[8][8];
    #pragma unroll
    for (int m = 0; m < 8; ++m)
        #pragma unroll
        for (int n = 0; n < 8; ++n) acc[m][n] = 0.f;

    for (int k0 = 0; k0 < kend; k0 += 16) {
        #pragma unroll
        for (int l = 0; l < 2; ++l) {
            int v   = tid + l * 256;
            int row = v >> 2;
            int c4  = (v & 3) * 4;
            float4 a = *(const float4*)&A[(size_t)(i0 + row) * K + k0 + c4];
            As[c4 + 0][row] = a.x; As[c4 + 1][row] = a.y;
            As[c4 + 2][row] = a.z; As[c4 + 3][row] = a.w;
            // B tile: 16 rows x 128 cols, contiguous in j.
            int kr = v >> 5;
            int jc = (v & 31) * 4;
            *(float4*)&Bs[kr][jc] = *(const float4*)&B[(size_t)(k0 + kr) * Nn + j0 + jc];
        }
        __syncthreads();

        #pragma unroll
        for (int kk = 0; kk < 16; ++kk) {
            float4 a0 = *(float4*)&As[kk][ty * 8];
            float4 a1 = *(float4*)&As[kk][ty * 8 + 4];
            float4 b0 = *(float4*)&Bs[kk][tx * 8];
            float4 b1 = *(float4*)&Bs[kk][tx * 8 + 4];
            float av[8] = {a0.x, a0.y, a0.z, a0.w, a1.x, a1.y, a1.z, a1.w};
            float bv[8] = {b0.x, b0.y, b0.z, b0.w, b1.x, b1.y, b1.z, b1.w};
            #pragma unroll
            for (int m = 0; m < 8; ++m)
                #pragma unroll
                for (int n = 0; n < 8; ++n)
                    acc[m][n] = fmaf(av[m], bv[n], acc[m][n]);
        }
        __syncthreads();
    }

    #pragma unroll
    for (int m = 0; m < 8; ++m) {
        size_t base = (size_t)(i0 + ty * 8 + m) * Nn + j0 + tx * 8;
        float4 w0 = make_float4(acc[m][0], acc[m][1], acc[m][2], acc[m][3]);
        float4 w1 = make_float4(acc[m][4], acc[m][5], acc[m][6], acc[m][7]);
        *(float4*)&C[base]     = w0;
        *(float4*)&C[base + 4] = w1;
    }
}

// ---------------------------------------------------------------------------
// Row softmax over NCTX entries, one block per row; the row (16 KB) stays in
// registers (16 floats/thread), single read + single write of g_s.
// Masked entries hold NEG_INF -> expf underflows to exactly 0.
// ---------------------------------------------------------------------------
__global__ __launch_bounds__(256)
void softmax_rows(float* __restrict__ S)
{
    const int row = blockIdx.x;
    const int tid = threadIdx.x;
    float* srow = S + (size_t)row * NCTX;

    float4 v[4];
    float vmax = NEG_INF;
    #pragma unroll
    for (int l = 0; l < 4; ++l) {
        v[l] = *(float4*)&srow[(tid + l * 256) * 4];
        vmax = fmaxf(vmax, fmaxf(fmaxf(v[l].x, v[l].y), fmaxf(v[l].z, v[l].w)));
    }

    __shared__ float red[256];
    red[tid] = vmax;
    __syncthreads();
    #pragma unroll
    for (int s = 128; s > 0; s >>= 1) {
        if (tid < s) red[tid] = fmaxf(red[tid], red[tid + s]);
        __syncthreads();
    }
    vmax = red[0];
    __syncthreads();

    float sum = 0.f;
    #pragma unroll
    for (int l = 0; l < 4; ++l) {
        v[l].x = expf(v[l].x - vmax);
        v[l].y = expf(v[l].y - vmax);
        v[l].z = expf(v[l].z - vmax);
        v[l].w = expf(v[l].w - vmax);
        sum += (v[l].x + v[l].y) + (v[l].z + v[l].w);
    }
    red[tid] = sum;
    __syncthreads();
    #pragma unroll
    for (int s = 128; s > 0; s >>= 1) {
        if (tid < s) red[tid] += red[tid + s];
        __syncthreads();
    }
    float inv = 1.f / red[0];

    #pragma unroll
    for (int l = 0; l < 4; ++l) {
        v[l].x *= inv; v[l].y *= inv; v[l].z *= inv; v[l].w *= inv;
        *(float4*)&srow[(tid + l * 256) * 4] = v[l];
    }
}

// ---------------------------------------------------------------------------

extern "C" void kernel_launch(void* const* d_in, const int* in_sizes, int n_in,
                              void* d_out, int out_size)
{
    const float* x   = (const float*)d_in[0];   // [4096, 2048]
    const float* Wqk = (const float*)d_in[1];   // [2048, 2048]
    const float* Wov = (const float*)d_in[2];   // [2048, 2048]
    float* out = (float*)d_out;                 // [4096, 2048]

    float *q, *s, *h;
    cudaGetSymbolAddress((void**)&q, g_q);
    cudaGetSymbolAddress((void**)&s, g_s);
    cudaGetSymbolAddress((void**)&h, g_h);

    dim3 blk(256);
    // q = x @ Wqk^T
    gemm_abt<false><<<dim3(DM / 128, NCTX / 128), blk>>>(x, Wqk, q, NCTX, DM, DM);
    // scores = q @ x^T  (+ causal mask)
    gemm_abt<true ><<<dim3(NCTX / 128, NCTX / 128), blk>>>(q, x, s, NCTX, NCTX, DM);
    // attn = softmax(scores) rowwise (in place)
    softmax_rows<<<NCTX, blk>>>(s);
    // h = attn @ x  (K loop clamped to lower triangle)
    gemm_ab<<<dim3(DM / 128, NCTX / 128), blk>>>(s, x, h, NCTX, DM, NCTX, 1);
    // out = h @ Wov^T
    gemm_abt<false><<<dim3(DM / 128, NCTX / 128), blk>>>(h, Wov, out, NCTX, DM, DM);
}